// round 17
// baseline (speedup 1.0000x reference)
#include <cuda_runtime.h>
#include <cuda_bf16.h>
#include <math.h>
#include <stdint.h>

// Problem constants
#define N_TOK 2048
#define M_TOK 2048
#define D_DIM 1024
#define C_DIM 768
#define H_HEADS 16
#define HD_DIM 64
#define FF_DIM 4096

// ---------------------------------------------------------------------------
// Scratch (static device globals)
// ---------------------------------------------------------------------------
__device__ float g_xq[N_TOK * D_DIM];
__device__ float g_kv[M_TOK * C_DIM];
__device__ float g_q [N_TOK * D_DIM];
__device__ float g_k [M_TOK * D_DIM];
__device__ float g_v [M_TOK * D_DIM];
__device__ float g_o [N_TOK * D_DIM];
__device__ float g_x1[N_TOK * D_DIM];
__device__ float g_hl[N_TOK * D_DIM];
__device__ float g_h1[N_TOK * FF_DIM];
// tf32-pre-rounded weights
__device__ float g_wq[D_DIM * D_DIM];
__device__ float g_wk[C_DIM * D_DIM];
__device__ float g_wv[C_DIM * D_DIM];
__device__ float g_wo[D_DIM * D_DIM];
__device__ float g_w1[D_DIM * FF_DIM];
__device__ float g_w2[FF_DIM * D_DIM];

// ---------------------------------------------------------------------------
// Helpers
// ---------------------------------------------------------------------------
__device__ __forceinline__ float gelu_tanh(float x) {
    const float k0 = 0.7978845608028654f;
    float x3 = x * x * x;
    return 0.5f * x * (1.0f + tanhf(k0 * (x + 0.044715f * x3)));
}

__device__ __forceinline__ float to_tf32(float x) {
    uint32_t t;
    asm("cvt.rna.tf32.f32 %0, %1;" : "=r"(t) : "f"(x));
    return __uint_as_float(t);
}

__device__ __forceinline__ void mma_tf32(float c[4], const uint32_t a[4],
                                         const uint32_t b[2]) {
    asm volatile(
        "mma.sync.aligned.m16n8k8.row.col.f32.tf32.tf32.f32 "
        "{%0,%1,%2,%3}, {%4,%5,%6,%7}, {%8,%9}, {%0,%1,%2,%3};"
        : "+f"(c[0]), "+f"(c[1]), "+f"(c[2]), "+f"(c[3])
        : "r"(a[0]), "r"(a[1]), "r"(a[2]), "r"(a[3]), "r"(b[0]), "r"(b[1]));
}

__device__ __forceinline__ void cp16(float* smem_dst, const float* gsrc) {
    uint32_t s = (uint32_t)__cvta_generic_to_shared(smem_dst);
    asm volatile("cp.async.cg.shared.global [%0], [%1], 16;" :: "r"(s), "l"(gsrc));
}
#define CP_COMMIT() asm volatile("cp.async.commit_group;")
#define CP_WAIT0()  asm volatile("cp.async.wait_group 0;")

// reduce across the 4 lanes of a quad group (tig dimension)
__device__ __forceinline__ float qreduce_max(float v) {
    v = fmaxf(v, __shfl_xor_sync(0xffffffffu, v, 1));
    v = fmaxf(v, __shfl_xor_sync(0xffffffffu, v, 2));
    return v;
}
__device__ __forceinline__ float qreduce_sum(float v) {
    v += __shfl_xor_sync(0xffffffffu, v, 1);
    v += __shfl_xor_sync(0xffffffffu, v, 2);
    return v;
}

__device__ __forceinline__ float blockReduceSum(float v) {
    __shared__ float s[32];
    __syncthreads();
    int lane = threadIdx.x & 31, wid = threadIdx.x >> 5;
    #pragma unroll
    for (int o = 16; o > 0; o >>= 1) v += __shfl_down_sync(0xffffffffu, v, o);
    if (lane == 0) s[wid] = v;
    __syncthreads();
    int nw = (blockDim.x + 31) >> 5;
    v = (threadIdx.x < nw) ? s[threadIdx.x] : 0.0f;
    if (wid == 0) {
        #pragma unroll
        for (int o = 16; o > 0; o >>= 1) v += __shfl_down_sync(0xffffffffu, v, o);
        if (lane == 0) s[0] = v;
    }
    __syncthreads();
    return s[0];
}

// ---------------------------------------------------------------------------
// tf32 pre-round: ALL six weight matrices in ONE launch (saturated grid)
// ---------------------------------------------------------------------------
__device__ __forceinline__ void round_seg(const float* __restrict__ in,
                                          float* __restrict__ out, int n4,
                                          int tid, int nthr)
{
    for (int i = tid; i < n4; i += nthr) {
        float4 v = reinterpret_cast<const float4*>(in)[i];
        v.x = to_tf32(v.x); v.y = to_tf32(v.y);
        v.z = to_tf32(v.z); v.w = to_tf32(v.w);
        reinterpret_cast<float4*>(out)[i] = v;
    }
}

__global__ void round_all_kernel(const float* s0, float* d0, int n0,
                                 const float* s1, float* d1, int n1,
                                 const float* s2, float* d2, int n2,
                                 const float* s3, float* d3, int n3,
                                 const float* s4, float* d4, int n4,
                                 const float* s5, float* d5, int n5)
{
    const int tid  = blockIdx.x * blockDim.x + threadIdx.x;
    const int nthr = gridDim.x * blockDim.x;
    round_seg(s0, d0, n0, tid, nthr);
    round_seg(s1, d1, n1, tid, nthr);
    round_seg(s2, d2, n2, tid, nthr);
    round_seg(s3, d3, n3, tid, nthr);
    round_seg(s4, d4, n4, tid, nthr);
    round_seg(s5, d5, n5, tid, nthr);
}

// ---------------------------------------------------------------------------
// LayerNorm: one block per row; output rounded to tf32 (feeds GEMM A-side)
// ---------------------------------------------------------------------------
__global__ void layernorm_kernel(const float* __restrict__ in,
                                 const float* __restrict__ w,
                                 const float* __restrict__ b,
                                 float* __restrict__ out, int cols)
{
    long row = blockIdx.x;
    const float* x = in + row * cols;
    float sum = 0.0f, sumsq = 0.0f;
    for (int i = threadIdx.x; i < cols; i += blockDim.x) {
        float v = x[i];
        sum += v;
        sumsq += v * v;
    }
    float tsum = blockReduceSum(sum);
    float tsq  = blockReduceSum(sumsq);
    float mean = tsum / cols;
    float var  = tsq / cols - mean * mean;
    float rstd = rsqrtf(var + 1e-12f);
    float* o = out + row * cols;
    for (int i = threadIdx.x; i < cols; i += blockDim.x) {
        o[i] = to_tf32((x[i] - mean) * rstd * w[i] + b[i]);
    }
}

// ---------------------------------------------------------------------------
// tf32 tensor-core GEMM, 2-stage cp.async pipeline, no cvt in inner loop
// (all operands pre-rounded to tf32 in gmem -> HW truncation exact).
// ---------------------------------------------------------------------------
template<int BM, int BN, int BK, int WARPS_M, int WARPS_N,
         bool BIAS, bool GELU, bool RES, bool ROUND>
__global__ __launch_bounds__(256, 2)
void mma_gemm(const float* __restrict__ A, const float* __restrict__ B,
              const float* __restrict__ bias, const float* __restrict__ res,
              float* __restrict__ C,
              int Kdim, int lda, int ldb, int ldc)
{
    extern __shared__ float smem[];
    constexpr int ASTR = BK + 4;
    constexpr int BS_C = BN + 8;
    constexpr int AOFF = 2 * BM * ASTR;

    constexpr int WM = BM / WARPS_M;
    constexpr int WN = BN / WARPS_N;
    constexpr int MT = WM / 16;
    constexpr int NT = WN / 8;

    const int m0 = blockIdx.y * BM;
    const int n0 = blockIdx.x * BN;

    const int tid  = threadIdx.x;
    const int warp = tid >> 5;
    const int lane = tid & 31;
    const int grp  = lane >> 2;
    const int tig  = lane & 3;
    const int wm0  = (warp / WARPS_N) * WM;
    const int wn0  = (warp % WARPS_N) * WN;

    float acc[MT][NT][4];
    #pragma unroll
    for (int i = 0; i < MT; i++)
        #pragma unroll
        for (int j = 0; j < NT; j++)
            #pragma unroll
            for (int r = 0; r < 4; r++) acc[i][j][r] = 0.0f;

    constexpr int A_V4 = BM * BK / 4;
    constexpr int B_V4 = BK * BN / 4;

    auto fill = [&](int buf, int k0) {
        float* Ab = smem + buf * BM * ASTR;
        #pragma unroll
        for (int it = 0; it < A_V4 / 256; it++) {
            int i  = tid + it * 256;
            int m  = i / (BK / 4);
            int kq = (i % (BK / 4)) * 4;
            cp16(&Ab[m * ASTR + kq], &A[(long)(m0 + m) * lda + k0 + kq]);
        }
        float* Bb = smem + AOFF + buf * BK * BS_C;
        #pragma unroll
        for (int it = 0; it < B_V4 / 256; it++) {
            int i  = tid + it * 256;
            int kk = i / (BN / 4);
            int n  = (i % (BN / 4)) * 4;
            cp16(&Bb[kk * BS_C + n], &B[(long)(k0 + kk) * ldb + n0 + n]);
        }
    };

    const int nt = Kdim / BK;
    fill(0, 0);
    CP_COMMIT();

    for (int t = 0; t < nt; t++) {
        CP_WAIT0();
        __syncthreads();
        if (t + 1 < nt) {
            fill((t + 1) & 1, (t + 1) * BK);
            CP_COMMIT();
        }
        const float* Ab = smem + (t & 1) * BM * ASTR;
        const float* Bb = smem + AOFF + (t & 1) * BK * BS_C;

        #pragma unroll
        for (int ks = 0; ks < BK / 8; ks++) {
            const int kb = ks * 8;
            uint32_t af[MT][4];
            #pragma unroll
            for (int mi = 0; mi < MT; mi++) {
                int r = wm0 + mi * 16 + grp;
                af[mi][0] = __float_as_uint(Ab[(r    ) * ASTR + kb + tig    ]);
                af[mi][1] = __float_as_uint(Ab[(r + 8) * ASTR + kb + tig    ]);
                af[mi][2] = __float_as_uint(Ab[(r    ) * ASTR + kb + tig + 4]);
                af[mi][3] = __float_as_uint(Ab[(r + 8) * ASTR + kb + tig + 4]);
            }
            uint32_t bf[NT][2];
            #pragma unroll
            for (int ni = 0; ni < NT; ni++) {
                int c = wn0 + ni * 8 + grp;
                bf[ni][0] = __float_as_uint(Bb[(kb + tig    ) * BS_C + c]);
                bf[ni][1] = __float_as_uint(Bb[(kb + tig + 4) * BS_C + c]);
            }
            #pragma unroll
            for (int mi = 0; mi < MT; mi++)
                #pragma unroll
                for (int ni = 0; ni < NT; ni++)
                    mma_tf32(acc[mi][ni], af[mi], bf[ni]);
        }
        __syncthreads();
    }

    // epilogue
    #pragma unroll
    for (int mi = 0; mi < MT; mi++) {
        #pragma unroll
        for (int ni = 0; ni < NT; ni++) {
            long r0 = m0 + wm0 + mi * 16 + grp;
            long r1 = r0 + 8;
            int  c0 = n0 + wn0 + ni * 8 + tig * 2;
            float v0 = acc[mi][ni][0];
            float v1 = acc[mi][ni][1];
            float v2 = acc[mi][ni][2];
            float v3 = acc[mi][ni][3];
            if (BIAS) {
                float bb0 = bias[c0], bb1 = bias[c0 + 1];
                v0 += bb0; v1 += bb1; v2 += bb0; v3 += bb1;
            }
            if (GELU) {
                v0 = gelu_tanh(v0); v1 = gelu_tanh(v1);
                v2 = gelu_tanh(v2); v3 = gelu_tanh(v3);
            }
            if (RES) {
                const float2 r0v = *reinterpret_cast<const float2*>(&res[r0 * ldc + c0]);
                const float2 r1v = *reinterpret_cast<const float2*>(&res[r1 * ldc + c0]);
                v0 += r0v.x; v1 += r0v.y; v2 += r1v.x; v3 += r1v.y;
            }
            if (ROUND) {
                v0 = to_tf32(v0); v1 = to_tf32(v1);
                v2 = to_tf32(v2); v3 = to_tf32(v3);
            }
            *reinterpret_cast<float2*>(&C[r0 * ldc + c0]) = make_float2(v0, v1);
            *reinterpret_cast<float2*>(&C[r1 * ldc + c0]) = make_float2(v2, v3);
        }
    }
}

// ---------------------------------------------------------------------------
// Flash attention (tf32 MMA, online softmax), double-buffered K/V via cp.async.
// One block = one head x 128 q rows. 8 warps; warp w owns q rows [16w,16w+16)
// and ALL 64 kv columns -> softmax row state is warp-private.
// smem: Qs[128][68] | 2xKs[64][68] | 2xVs[64][72] | Ps[128][68] = 138 KB
// Buffer hazard: fill of buf b at iter t+1 is issued after the top-of-loop
// wait+syncthreads; buf b was last read at iter t-1 -> safe with one barrier.
// ---------------------------------------------------------------------------
#define FA_BQ  128
#define FA_BKV 64
#define QS_STR 68
#define KS_STR 68
#define VS_STR 72
#define PS_STR 68

__global__ __launch_bounds__(256, 1)
void flash_attn(const float* __restrict__ q, const float* __restrict__ k,
                const float* __restrict__ v, float* __restrict__ o)
{
    extern __shared__ float smem[];
    float* sQ = smem;                                  // 128*68
    float* sK = sQ + FA_BQ * QS_STR;                   // 2 x 64*68
    float* sV = sK + 2 * FA_BKV * KS_STR;              // 2 x 64*72
    float* sP = sV + 2 * FA_BKV * VS_STR;              // 128*68

    const int h  = blockIdx.y;
    const int q0 = blockIdx.x * FA_BQ;
    const float* qh = q + (size_t)q0 * D_DIM + h * HD_DIM;
    const float* kh = k + h * HD_DIM;
    const float* vh = v + h * HD_DIM;

    const int tid  = threadIdx.x;
    const int warp = tid >> 5;
    const int lane = tid & 31;
    const int grp  = lane >> 2;
    const int tig  = lane & 3;
    const int wm0  = warp * 16;

    auto fillKV = [&](int buf, int t0) {
        float* Kb = sK + buf * FA_BKV * KS_STR;
        float* Vb = sV + buf * FA_BKV * VS_STR;
        #pragma unroll
        for (int it = 0; it < 4; it++) {
            int i  = tid + it * 256;
            int r  = i >> 4;
            int kq = (i & 15) * 4;
            cp16(&Kb[r * KS_STR + kq], &kh[(size_t)(t0 + r) * D_DIM + kq]);
            cp16(&Vb[r * VS_STR + kq], &vh[(size_t)(t0 + r) * D_DIM + kq]);
        }
    };

    // kick off first K/V tile load, then fill Q while it flies
    fillKV(0, 0);
    CP_COMMIT();

    #pragma unroll
    for (int it = 0; it < 8; it++) {
        int i  = tid + it * 256;
        int m  = i >> 4;
        int kq = (i & 15) * 4;
        float4 qv = *reinterpret_cast<const float4*>(&qh[(size_t)m * D_DIM + kq]);
        sQ[m * QS_STR + kq + 0] = qv.x * 0.125f;   // tf32 values, /8 exact
        sQ[m * QS_STR + kq + 1] = qv.y * 0.125f;
        sQ[m * QS_STR + kq + 2] = qv.z * 0.125f;
        sQ[m * QS_STR + kq + 3] = qv.w * 0.125f;
    }

    float m_i[2] = {-1e30f, -1e30f};
    float l_i[2] = {0.0f, 0.0f};
    float oacc[8][4];
    #pragma unroll
    for (int ni = 0; ni < 8; ni++)
        #pragma unroll
        for (int r = 0; r < 4; r++) oacc[ni][r] = 0.0f;

    const int NTILES = M_TOK / FA_BKV;
    for (int t = 0; t < NTILES; t++) {
        CP_WAIT0();
        __syncthreads();
        if (t + 1 < NTILES) {
            fillKV((t + 1) & 1, (t + 1) * FA_BKV);
            CP_COMMIT();
        }
        const float* Kb = sK + (t & 1) * FA_BKV * KS_STR;
        const float* Vb = sV + (t & 1) * FA_BKV * VS_STR;

        // S = Qs @ Kb^T  (warp tile 16 x 64, K=64)
        float sacc[8][4];
        #pragma unroll
        for (int ni = 0; ni < 8; ni++)
            #pragma unroll
            for (int r = 0; r < 4; r++) sacc[ni][r] = 0.0f;

        #pragma unroll
        for (int ks = 0; ks < 8; ks++) {
            const int kb = ks * 8;
            uint32_t af[4];
            af[0] = __float_as_uint(sQ[(wm0 + grp    ) * QS_STR + kb + tig    ]);
            af[1] = __float_as_uint(sQ[(wm0 + grp + 8) * QS_STR + kb + tig    ]);
            af[2] = __float_as_uint(sQ[(wm0 + grp    ) * QS_STR + kb + tig + 4]);
            af[3] = __float_as_uint(sQ[(wm0 + grp + 8) * QS_STR + kb + tig + 4]);
            #pragma unroll
            for (int ni = 0; ni < 8; ni++) {
                uint32_t bf[2];
                int c = ni * 8 + grp;
                bf[0] = __float_as_uint(Kb[c * KS_STR + kb + tig    ]);
                bf[1] = __float_as_uint(Kb[c * KS_STR + kb + tig + 4]);
                mma_tf32(sacc[ni], af, bf);
            }
        }

        // online softmax (rows warp-private)
        #pragma unroll
        for (int half = 0; half < 2; half++) {
            float mx = -1e30f;
            #pragma unroll
            for (int ni = 0; ni < 8; ni++)
                mx = fmaxf(mx, fmaxf(sacc[ni][2*half], sacc[ni][2*half+1]));
            mx = qreduce_max(mx);
            float mold = m_i[half];
            float mnew = fmaxf(mold, mx);
            float scale = __expf(mold - mnew);
            m_i[half] = mnew;

            int row = wm0 + grp + half * 8;
            float rsum = 0.0f;
            #pragma unroll
            for (int ni = 0; ni < 8; ni++) {
                float p0 = __expf(sacc[ni][2*half    ] - mnew);
                float p1 = __expf(sacc[ni][2*half + 1] - mnew);
                rsum += p0 + p1;
                *reinterpret_cast<float2*>(&sP[row * PS_STR + ni * 8 + 2 * tig]) =
                    make_float2(to_tf32(p0), to_tf32(p1));
            }
            rsum = qreduce_sum(rsum);
            l_i[half] = l_i[half] * scale + rsum;
            #pragma unroll
            for (int ni = 0; ni < 8; ni++) {
                oacc[ni][2*half    ] *= scale;
                oacc[ni][2*half + 1] *= scale;
            }
        }
        __syncwarp();

        // O += Ps @ Vb
        #pragma unroll
        for (int ks = 0; ks < 8; ks++) {
            const int kb = ks * 8;
            uint32_t af[4];
            af[0] = __float_as_uint(sP[(wm0 + grp    ) * PS_STR + kb + tig    ]);
            af[1] = __float_as_uint(sP[(wm0 + grp + 8) * PS_STR + kb + tig    ]);
            af[2] = __float_as_uint(sP[(wm0 + grp    ) * PS_STR + kb + tig + 4]);
            af[3] = __float_as_uint(sP[(wm0 + grp + 8) * PS_STR + kb + tig + 4]);
            #pragma unroll
            for (int ni = 0; ni < 8; ni++) {
                uint32_t bf[2];
                int c = ni * 8 + grp;
                bf[0] = __float_as_uint(Vb[(kb + tig    ) * VS_STR + c]);
                bf[1] = __float_as_uint(Vb[(kb + tig + 4) * VS_STR + c]);
                mma_tf32(oacc[ni], af, bf);
            }
        }
        // no trailing barrier: next iteration's wait+syncthreads protects buffers
    }

    // epilogue: O /= l, round to tf32 (feeds O-proj GEMM)
    float inv0 = 1.0f / l_i[0];
    float inv1 = 1.0f / l_i[1];
    long r0 = q0 + wm0 + grp;
    long r1 = r0 + 8;
    #pragma unroll
    for (int ni = 0; ni < 8; ni++) {
        int c0 = h * HD_DIM + ni * 8 + 2 * tig;
        *reinterpret_cast<float2*>(&o[r0 * D_DIM + c0]) =
            make_float2(to_tf32(oacc[ni][0] * inv0), to_tf32(oacc[ni][1] * inv0));
        *reinterpret_cast<float2*>(&o[r1 * D_DIM + c0]) =
            make_float2(to_tf32(oacc[ni][2] * inv1), to_tf32(oacc[ni][3] * inv1));
    }
}

// ---------------------------------------------------------------------------
// Launch
// ---------------------------------------------------------------------------
#define GEMM_SMEM ((2 * 128 * 36 + 2 * 32 * 136) * 4)          // 71680
#define FA_SMEM   ((FA_BQ * QS_STR + 2 * FA_BKV * KS_STR + 2 * FA_BKV * VS_STR \
                    + FA_BQ * PS_STR) * 4)                      // 141312

extern "C" void kernel_launch(void* const* d_in, const int* in_sizes, int n_in,
                              void* d_out, int out_size)
{
    const float* x    = (const float*)d_in[0];
    const float* ctx  = (const float*)d_in[1];
    const float* wq   = (const float*)d_in[2];
    const float* bq   = (const float*)d_in[3];
    const float* wk   = (const float*)d_in[4];
    const float* bk   = (const float*)d_in[5];
    const float* wv   = (const float*)d_in[6];
    const float* bv   = (const float*)d_in[7];
    const float* wo   = (const float*)d_in[8];
    const float* bo   = (const float*)d_in[9];
    const float* w1   = (const float*)d_in[10];
    const float* b1   = (const float*)d_in[11];
    const float* w2   = (const float*)d_in[12];
    const float* b2   = (const float*)d_in[13];
    const float* qn_w = (const float*)d_in[14];
    const float* qn_b = (const float*)d_in[15];
    const float* kvn_w= (const float*)d_in[16];
    const float* kvn_b= (const float*)d_in[17];
    const float* pn_w = (const float*)d_in[18];
    const float* pn_b = (const float*)d_in[19];
    float* out = (float*)d_out;

    float *xq, *kv, *q, *k, *v, *o, *x1, *hl, *h1;
    float *wqr, *wkr, *wvr, *wor, *w1r, *w2r;
    cudaGetSymbolAddress((void**)&xq, g_xq);
    cudaGetSymbolAddress((void**)&kv, g_kv);
    cudaGetSymbolAddress((void**)&q,  g_q);
    cudaGetSymbolAddress((void**)&k,  g_k);
    cudaGetSymbolAddress((void**)&v,  g_v);
    cudaGetSymbolAddress((void**)&o,  g_o);
    cudaGetSymbolAddress((void**)&x1, g_x1);
    cudaGetSymbolAddress((void**)&hl, g_hl);
    cudaGetSymbolAddress((void**)&h1, g_h1);
    cudaGetSymbolAddress((void**)&wqr, g_wq);
    cudaGetSymbolAddress((void**)&wkr, g_wk);
    cudaGetSymbolAddress((void**)&wvr, g_wv);
    cudaGetSymbolAddress((void**)&wor, g_wo);
    cudaGetSymbolAddress((void**)&w1r, g_w1);
    cudaGetSymbolAddress((void**)&w2r, g_w2);

    auto kProjR = mma_gemm<128,128,32,2,4,true,false,false,true>;
    auto kRes   = mma_gemm<128,128,32,2,4,true,false,true,false>;
    auto kGeluR = mma_gemm<128,128,32,2,4,true,true,false,true>;
    cudaFuncSetAttribute(kProjR, cudaFuncAttributeMaxDynamicSharedMemorySize, GEMM_SMEM);
    cudaFuncSetAttribute(kRes,   cudaFuncAttributeMaxDynamicSharedMemorySize, GEMM_SMEM);
    cudaFuncSetAttribute(kGeluR, cudaFuncAttributeMaxDynamicSharedMemorySize, GEMM_SMEM);
    cudaFuncSetAttribute(flash_attn, cudaFuncAttributeMaxDynamicSharedMemorySize, FA_SMEM);

    // 0) pre-round all weights to tf32 — ONE saturated launch
    round_all_kernel<<<2048, 256>>>(
        wq, wqr, D_DIM * D_DIM / 4,
        wk, wkr, C_DIM * D_DIM / 4,
        wv, wvr, C_DIM * D_DIM / 4,
        wo, wor, D_DIM * D_DIM / 4,
        w1, w1r, D_DIM * FF_DIM / 4,
        w2, w2r, FF_DIM * D_DIM / 4);

    // 1) pre-norms (tf32-rounded outputs)
    layernorm_kernel<<<N_TOK, 256>>>(x,   qn_w,  qn_b,  xq, D_DIM);
    layernorm_kernel<<<M_TOK, 256>>>(ctx, kvn_w, kvn_b, kv, C_DIM);

    // 2) Q/K/V projections (tf32-rounded outputs -> FA)
    {
        dim3 g(D_DIM / 128, N_TOK / 128, 1);
        kProjR<<<g, 256, GEMM_SMEM>>>(xq, wqr, bq, nullptr, q, D_DIM,
                                      D_DIM, D_DIM, D_DIM);
    }
    {
        dim3 g(D_DIM / 128, M_TOK / 128, 1);
        kProjR<<<g, 256, GEMM_SMEM>>>(kv, wkr, bk, nullptr, k, C_DIM,
                                      C_DIM, D_DIM, D_DIM);
        kProjR<<<g, 256, GEMM_SMEM>>>(kv, wvr, bv, nullptr, v, C_DIM,
                                      C_DIM, D_DIM, D_DIM);
    }

    // 3) fused attention
    {
        dim3 g(N_TOK / FA_BQ, H_HEADS, 1);
        flash_attn<<<g, 256, FA_SMEM>>>(q, k, v, o);
    }

    // 4) x1 = o @ wo + bo + x   (full fp32, residual)
    {
        dim3 g(D_DIM / 128, N_TOK / 128, 1);
        kRes<<<g, 256, GEMM_SMEM>>>(o, wor, bo, x, x1, D_DIM,
                                    D_DIM, D_DIM, D_DIM);
    }
    // 5) hl = LN(x1)  (tf32-rounded)
    layernorm_kernel<<<N_TOK, 256>>>(x1, pn_w, pn_b, hl, D_DIM);

    // 6) h1 = gelu(hl @ w1 + b1)  (tf32-rounded)
    {
        dim3 g(FF_DIM / 128, N_TOK / 128, 1);
        kGeluR<<<g, 256, GEMM_SMEM>>>(hl, w1r, b1, nullptr, h1, D_DIM,
                                      D_DIM, FF_DIM, FF_DIM);
    }
    // 7) out = h1 @ w2 + b2 + x1  (full fp32)
    {
        dim3 g(D_DIM / 128, N_TOK / 128, 1);
        kRes<<<g, 256, GEMM_SMEM>>>(h1, w2r, b2, x1, out, FF_DIM,
                                    FF_DIM, D_DIM, D_DIM);
    }
}